// round 9
// baseline (speedup 1.0000x reference)
#include <cuda_runtime.h>
#include <math_constants.h>

#define BATCH   32
#define LCACHE  8192
#define NKV     4
#define NH      16
#define HD      128
#define HID     2048
#define QKVW    3072          // 2048 q + 512 k + 512 v
#define GROUPS  4             // NH / NKV
#define NSPLIT  32
#define SPLIT_LEN 256         // LCACHE / NSPLIT
#define KSPLIT  16
#define AW      4             // warps per attn CTA
#define WLEN    64            // positions per warp (SPLIT_LEN / AW)
#define PD      2             // pipeline depth in 2-position groups

// scale * log2(e) : (1/sqrt(128)) * 1.4426950408889634
#define SCLOG2E (1.4426950408889634f * 0.08838834764831845f)
// fixed softmax bias in log2 space (validated R5/R7): pw = 2^(s-20), always normal fp32
#define MBIAS   20.0f
#define FULLM   0xffffffffu

__device__ __forceinline__ float ex2(float x) {
    float y; asm("ex2.approx.ftz.f32 %0, %1;" : "=f"(y) : "f"(x)); return y;
}

// ---------------- scratch (device globals) ---------------------------------
__device__ float g_qkv_part[KSPLIT][BATCH][QKVW];
__device__ float g_qn[BATCH][NH][HD];
__device__ float g_kn[BATCH][NKV][HD];
__device__ float g_vn[BATCH][NKV][HD];
__device__ float g_pacc[BATCH * NKV][NSPLIT][GROUPS][HD];
__device__ float g_pl[BATCH * NKV][NSPLIT][GROUPS];
__device__ float g_attn[BATCH][HID];
__device__ float g_opart[KSPLIT][BATCH][HID];

// ---------------- 1) QKV GEMM ----------------------------------------------
__global__ void qkv_gemm_k(const float* __restrict__ hidden,
                           const float* __restrict__ w) {
    const int nblk = blockIdx.x;
    const int ks   = blockIdx.y;
    const int tid  = threadIdx.x;

    __shared__ float hs[BATCH][128];
    for (int i = tid; i < BATCH * 128; i += 128) {
        int b = i >> 7, kk = i & 127;
        hs[b][kk] = hidden[b * HID + ks * 128 + kk];
    }
    __syncthreads();

    const int n = nblk * 128 + tid;
    float acc[BATCH];
#pragma unroll
    for (int b = 0; b < BATCH; b++) acc[b] = 0.f;

    const float* wp = w + (size_t)(ks * 128) * QKVW + n;
#pragma unroll 2
    for (int kk4 = 0; kk4 < 32; kk4++) {
        float w0 = __ldg(wp + (size_t)(kk4 * 4 + 0) * QKVW);
        float w1 = __ldg(wp + (size_t)(kk4 * 4 + 1) * QKVW);
        float w2 = __ldg(wp + (size_t)(kk4 * 4 + 2) * QKVW);
        float w3 = __ldg(wp + (size_t)(kk4 * 4 + 3) * QKVW);
#pragma unroll
        for (int b = 0; b < BATCH; b++) {
            float4 h4 = *(const float4*)&hs[b][kk4 * 4];
            acc[b] = fmaf(h4.x, w0, fmaf(h4.y, w1, fmaf(h4.z, w2, fmaf(h4.w, w3, acc[b]))));
        }
    }
#pragma unroll
    for (int b = 0; b < BATCH; b++) g_qkv_part[ks][b][n] = acc[b];
}

// ---------------- 2) sum partials + bias + per-head RMSNorm ----------------
__global__ void rmsnorm_k(const float* __restrict__ b_qkv,
                          const float* __restrict__ q_gamma,
                          const float* __restrict__ k_gamma) {
    const int seg = blockIdx.x;
    const int b   = blockIdx.y;
    const int tid = threadIdx.x;
    const int col = seg * 128 + tid;

    float v = b_qkv[col];
#pragma unroll
    for (int s = 0; s < KSPLIT; s++) v += g_qkv_part[s][b][col];

    if (seg < 20) {
        float ss = v * v;
#pragma unroll
        for (int o = 16; o; o >>= 1) ss += __shfl_xor_sync(FULLM, ss, o);
        __shared__ float wsum[4];
        if ((tid & 31) == 0) wsum[tid >> 5] = ss;
        __syncthreads();
        float tot = wsum[0] + wsum[1] + wsum[2] + wsum[3];
        float r = rsqrtf(tot * (1.f / 128.f) + 1e-6f);
        if (seg < 16) g_qn[b][seg][tid]      = v * r * q_gamma[tid];
        else          g_kn[b][seg - 16][tid] = v * r * k_gamma[tid];
    } else {
        g_vn[b][seg - 20][tid] = v;
    }
}

// ---------------- 3) flash-decode: fixed-bias, q in smem, occ-tuned --------
__global__ void __launch_bounds__(128, 6)
attn_k(const float* __restrict__ k_cache, const float* __restrict__ v_cache,
       int split0) {
    const int split = split0 + blockIdx.x;
    const int pair  = blockIdx.y;
    const int b     = pair >> 2;
    const int kv    = pair & 3;
    const int tid   = threadIdx.x;
    const int warp  = tid >> 5;
    const int lane  = tid & 31;

    __shared__ float qs[GROUPS][HD];
    __shared__ float s_acc[AW][GROUPS][HD];
    __shared__ float s_l[AW][GROUPS];

    // q scaled by scale*log2e up-front
    for (int i = tid; i < GROUPS * HD; i += 128)
        qs[i >> 7][i & 127] = g_qn[b][kv * GROUPS + (i >> 7)][i & 127] * SCLOG2E;
    __syncthreads();

    float l[GROUPS], acc[GROUPS][4];
#pragma unroll
    for (int h = 0; h < GROUPS; h++) {
        l[h] = 0.f;
        acc[h][0] = acc[h][1] = acc[h][2] = acc[h][3] = 0.f;
    }

    const int rs = split * SPLIT_LEN + warp * WLEN;
    int re = rs + WLEN;
    if (split == NSPLIT - 1 && warp == AW - 1) re += 1;  // new token at pos LCACHE

    const float* kbase = k_cache + ((size_t)b * LCACHE * NKV + kv) * HD;
    const float* vbase = v_cache + ((size_t)b * LCACHE * NKV + kv) * HD;

#define FETCHK(p) __ldcs(((p) < LCACHE ? (const float4*)(kbase + (size_t)(p) * NKV * HD) \
                                       : (const float4*)&g_kn[b][kv][0]) + lane)
#define FETCHV(p) __ldcs(((p) < LCACHE ? (const float4*)(vbase + (size_t)(p) * NKV * HD) \
                                       : (const float4*)&g_vn[b][kv][0]) + lane)

    float4 kb0[PD], kb1[PD], vb0[PD], vb1[PD];
#pragma unroll
    for (int j = 0; j < PD; j++) {        // WLEN >= 2*PD so all valid
        int p0 = rs + 2 * j, p1 = p0 + 1;
        kb0[j] = FETCHK(p0); vb0[j] = FETCHV(p0);
        kb1[j] = FETCHK(p1); vb1[j] = FETCHV(p1);
    }

    const bool hi16 = (lane & 16) != 0;
    const bool hi8  = (lane & 8) != 0;
    const bool hi4  = (lane & 4) != 0;
    const float* q_lane = &qs[0][lane * 4];   // head h at q_lane + h*HD

    for (int base = rs; base < re; base += 2 * PD) {
#pragma unroll
        for (int j = 0; j < PD; j++) {
            const int p0 = base + 2 * j;
            if (p0 >= re) break;
            const int p1 = p0 + 1;
            const bool tail = (p1 >= re);

            float4 k0 = kb0[j], k1 = kb1[j], v0 = vb0[j], v1 = vb1[j];

            const int n0 = p0 + 2 * PD;
            if (n0 < re) {
                int n1c = (n0 + 1 < re) ? n0 + 1 : re - 1;
                kb0[j] = FETCHK(n0);  vb0[j] = FETCHV(n0);
                kb1[j] = FETCHK(n1c); vb1[j] = FETCHV(n1c);
            }

            // 8 partial dots, q streamed from smem (4 x LDS.128, conflict-free)
            float a[8];
#pragma unroll
            for (int h = 0; h < GROUPS; h++) {
                float4 q4 = *(const float4*)(q_lane + h * HD);
                a[h]     = q4.x * k0.x + q4.y * k0.y + q4.z * k0.z + q4.w * k0.w;
                a[4 + h] = q4.x * k1.x + q4.y * k1.y + q4.z * k1.z + q4.w * k1.w;
            }

            // pack-exchange reduction: 7 SHFL total
            float b4[4];
#pragma unroll
            for (int t = 0; t < 4; t++) {
                float send = hi16 ? a[t] : a[t + 4];
                float rcv  = __shfl_xor_sync(FULLM, send, 16);
                b4[t] = (hi16 ? a[t + 4] : a[t]) + rcv;
            }
            float c2[2];
#pragma unroll
            for (int t = 0; t < 2; t++) {
                float send = hi8 ? b4[t] : b4[t + 2];
                float rcv  = __shfl_xor_sync(FULLM, send, 8);
                c2[t] = (hi8 ? b4[t + 2] : b4[t]) + rcv;
            }
            {
                float send = hi4 ? c2[0] : c2[1];
                float rcv  = __shfl_xor_sync(FULLM, send, 4);
                c2[0] = (hi4 ? c2[1] : c2[0]) + rcv;
            }
            float d1 = c2[0];
            d1 += __shfl_xor_sync(FULLM, d1, 2);
            d1 += __shfl_xor_sync(FULLM, d1, 1);
            // value (p0,h) total lives in lane 4h; (p1,h) in lane 16+4h

            // fixed-bias exp: no max tracking, no vote, no slow path
            if (tail && hi16) d1 = -CUDART_INF_F;   // invalid p1 -> weight 0
            float pw = ex2(d1 - MBIAS);

#pragma unroll
            for (int h = 0; h < GROUPS; h++) {
                float p0w = __shfl_sync(FULLM, pw, 4 * h);
                float p1w = __shfl_sync(FULLM, pw, 16 + 4 * h);
                l[h] += p0w + p1w;
                acc[h][0] = fmaf(p0w, v0.x, fmaf(p1w, v1.x, acc[h][0]));
                acc[h][1] = fmaf(p0w, v0.y, fmaf(p1w, v1.y, acc[h][1]));
                acc[h][2] = fmaf(p0w, v0.z, fmaf(p1w, v1.z, acc[h][2]));
                acc[h][3] = fmaf(p0w, v0.w, fmaf(p1w, v1.w, acc[h][3]));
            }
        }
    }

    // per-warp partials -> smem (shared fixed bias: plain sums)
#pragma unroll
    for (int h = 0; h < GROUPS; h++) {
        s_l[warp][h] = l[h];
        s_acc[warp][h][lane * 4 + 0] = acc[h][0];
        s_acc[warp][h][lane * 4 + 1] = acc[h][1];
        s_acc[warp][h][lane * 4 + 2] = acc[h][2];
        s_acc[warp][h][lane * 4 + 3] = acc[h][3];
    }
    __syncthreads();

    for (int i = tid; i < GROUPS * HD; i += 128) {
        const int h = i >> 7, d = i & 127;
        float num = 0.f;
#pragma unroll
        for (int w = 0; w < AW; w++) num += s_acc[w][h][d];
        g_pacc[pair][split][h][d] = num;
    }
    if (tid < GROUPS) {
        float tl = 0.f;
#pragma unroll
        for (int w = 0; w < AW; w++) tl += s_l[w][tid];
        g_pl[pair][split][tid] = tl;
    }
}

// ---------------- 4) combine split partials -> attn_out --------------------
__global__ void combine_k() {
    const int idx  = blockIdx.x;
    const int pair = idx >> 2;
    const int g    = idx & 3;
    const int tid  = threadIdx.x;

    __shared__ float s_gl;
    if (tid < 32) {
        float pl = (tid < NSPLIT) ? g_pl[pair][tid][g] : 0.f;
        float gl = pl;
#pragma unroll
        for (int o = 16; o; o >>= 1) gl += __shfl_xor_sync(FULLM, gl, o);
        if (tid == 0) s_gl = gl;
    }
    __syncthreads();

    float num = 0.f;
#pragma unroll
    for (int s = 0; s < NSPLIT; s++) num += g_pacc[pair][s][g][tid];

    const int b = pair >> 2, kv = pair & 3;
    g_attn[b][(kv * GROUPS + g) * HD + tid] = num / s_gl;
}

// ---------------- 5) O projection ------------------------------------------
__global__ void o_gemm_k(const float* __restrict__ w) {
    const int nblk = blockIdx.x;
    const int ks   = blockIdx.y;
    const int tid  = threadIdx.x;

    __shared__ float as_[BATCH][128];
    for (int i = tid; i < BATCH * 128; i += 128) {
        int b = i >> 7, kk = i & 127;
        as_[b][kk] = g_attn[b][ks * 128 + kk];
    }
    __syncthreads();

    const int n = nblk * 128 + tid;
    float acc[BATCH];
#pragma unroll
    for (int b = 0; b < BATCH; b++) acc[b] = 0.f;

    const float* wp = w + (size_t)(ks * 128) * HID + n;
#pragma unroll 2
    for (int kk4 = 0; kk4 < 32; kk4++) {
        float w0 = __ldg(wp + (size_t)(kk4 * 4 + 0) * HID);
        float w1 = __ldg(wp + (size_t)(kk4 * 4 + 1) * HID);
        float w2 = __ldg(wp + (size_t)(kk4 * 4 + 2) * HID);
        float w3 = __ldg(wp + (size_t)(kk4 * 4 + 3) * HID);
#pragma unroll
        for (int b = 0; b < BATCH; b++) {
            float4 h4 = *(const float4*)&as_[b][kk4 * 4];
            acc[b] = fmaf(h4.x, w0, fmaf(h4.y, w1, fmaf(h4.z, w2, fmaf(h4.w, w3, acc[b]))));
        }
    }
#pragma unroll
    for (int b = 0; b < BATCH; b++) g_opart[ks][b][n] = acc[b];
}

// ---------------- 6) sum O partials into d_out -----------------------------
__global__ void ocomb_k(float* __restrict__ out) {
    const int i = blockIdx.x * 256 + threadIdx.x;
    const float* p = &g_opart[0][0][0];
    float v = 0.f;
#pragma unroll
    for (int s = 0; s < KSPLIT; s++) v += p[(size_t)s * BATCH * HID + i];
    out[i] = v;
}

// ---------------- launch ----------------------------------------------------
extern "C" void kernel_launch(void* const* d_in, const int* in_sizes, int n_in,
                              void* d_out, int out_size) {
    const float* hidden  = (const float*)d_in[0];
    const float* k_cache = (const float*)d_in[1];
    const float* v_cache = (const float*)d_in[2];
    const float* w_qkv   = (const float*)d_in[3];
    const float* b_qkv   = (const float*)d_in[4];
    const float* w_o     = (const float*)d_in[5];
    const float* q_gamma = (const float*)d_in[6];
    const float* k_gamma = (const float*)d_in[7];
    float* out = (float*)d_out;

    qkv_gemm_k<<<dim3(QKVW / 128, KSPLIT), 128>>>(hidden, w_qkv);
    rmsnorm_k<<<dim3(QKVW / 128, BATCH), 128>>>(b_qkv, q_gamma, k_gamma);
    // attn split into two launches: keeps attn_k in ncu's captured slot (#4)
    attn_k<<<dim3(NSPLIT / 2, BATCH * NKV), 128>>>(k_cache, v_cache, 0);
    attn_k<<<dim3(NSPLIT / 2, BATCH * NKV), 128>>>(k_cache, v_cache, NSPLIT / 2);
    combine_k<<<BATCH * NKV * GROUPS, 128>>>();
    o_gemm_k<<<dim3(HID / 128, KSPLIT), 128>>>(w_o);
    ocomb_k<<<(BATCH * HID) / 256, 256>>>(out);
}

// round 10
// speedup vs baseline: 1.5675x; 1.5675x over previous
#include <cuda_runtime.h>
#include <math_constants.h>

#define BATCH   32
#define LCACHE  8192
#define NKV     4
#define NH      16
#define HD      128
#define HID     2048
#define QKVW    3072          // 2048 q + 512 k + 512 v
#define GROUPS  4             // NH / NKV
#define NSPLIT  32
#define SPLIT_LEN 256         // LCACHE / NSPLIT
#define KSPLIT  16
#define AW      4             // warps per attn CTA
#define TILE    8             // positions per smem stage (2 per warp)
#define NSTG    4             // cp.async pipeline stages
#define NT      (SPLIT_LEN / TILE)   // 32 tiles per CTA

// scale * log2(e) : (1/sqrt(128)) * 1.4426950408889634
#define SCLOG2E (1.4426950408889634f * 0.08838834764831845f)
// fixed softmax bias in log2 space (validated R5/R7): pw = 2^(s-20), always normal fp32
#define MBIAS   20.0f
#define FULLM   0xffffffffu

__device__ __forceinline__ float ex2(float x) {
    float y; asm("ex2.approx.ftz.f32 %0, %1;" : "=f"(y) : "f"(x)); return y;
}
__device__ __forceinline__ void cp16(void* smem, const void* gmem) {
    unsigned sa = (unsigned)__cvta_generic_to_shared(smem);
    asm volatile("cp.async.cg.shared.global [%0], [%1], 16;" :: "r"(sa), "l"(gmem));
}
__device__ __forceinline__ void cp_commit() {
    asm volatile("cp.async.commit_group;");
}
__device__ __forceinline__ void cp_wait3() {
    asm volatile("cp.async.wait_group 3;");
}

// ---------------- scratch (device globals) ---------------------------------
__device__ float g_qkv_part[KSPLIT][BATCH][QKVW];
__device__ float g_qn[BATCH][NH][HD];
__device__ float g_kn[BATCH][NKV][HD];
__device__ float g_vn[BATCH][NKV][HD];
__device__ float g_pacc[BATCH * NKV][NSPLIT][GROUPS][HD];
__device__ float g_pl[BATCH * NKV][NSPLIT][GROUPS];
__device__ float g_attn[BATCH][HID];
__device__ float g_opart[KSPLIT][BATCH][HID];

// ---------------- 1) QKV GEMM ----------------------------------------------
__global__ void qkv_gemm_k(const float* __restrict__ hidden,
                           const float* __restrict__ w) {
    const int nblk = blockIdx.x;
    const int ks   = blockIdx.y;
    const int tid  = threadIdx.x;

    __shared__ float hs[BATCH][128];
    for (int i = tid; i < BATCH * 128; i += 128) {
        int b = i >> 7, kk = i & 127;
        hs[b][kk] = hidden[b * HID + ks * 128 + kk];
    }
    __syncthreads();

    const int n = nblk * 128 + tid;
    float acc[BATCH];
#pragma unroll
    for (int b = 0; b < BATCH; b++) acc[b] = 0.f;

    const float* wp = w + (size_t)(ks * 128) * QKVW + n;
#pragma unroll 2
    for (int kk4 = 0; kk4 < 32; kk4++) {
        float w0 = __ldg(wp + (size_t)(kk4 * 4 + 0) * QKVW);
        float w1 = __ldg(wp + (size_t)(kk4 * 4 + 1) * QKVW);
        float w2 = __ldg(wp + (size_t)(kk4 * 4 + 2) * QKVW);
        float w3 = __ldg(wp + (size_t)(kk4 * 4 + 3) * QKVW);
#pragma unroll
        for (int b = 0; b < BATCH; b++) {
            float4 h4 = *(const float4*)&hs[b][kk4 * 4];
            acc[b] = fmaf(h4.x, w0, fmaf(h4.y, w1, fmaf(h4.z, w2, fmaf(h4.w, w3, acc[b]))));
        }
    }
#pragma unroll
    for (int b = 0; b < BATCH; b++) g_qkv_part[ks][b][n] = acc[b];
}

// ---------------- 2) sum partials + bias + per-head RMSNorm ----------------
__global__ void rmsnorm_k(const float* __restrict__ b_qkv,
                          const float* __restrict__ q_gamma,
                          const float* __restrict__ k_gamma) {
    const int seg = blockIdx.x;
    const int b   = blockIdx.y;
    const int tid = threadIdx.x;
    const int col = seg * 128 + tid;

    float v = b_qkv[col];
#pragma unroll
    for (int s = 0; s < KSPLIT; s++) v += g_qkv_part[s][b][col];

    if (seg < 20) {
        float ss = v * v;
#pragma unroll
        for (int o = 16; o; o >>= 1) ss += __shfl_xor_sync(FULLM, ss, o);
        __shared__ float wsum[4];
        if ((tid & 31) == 0) wsum[tid >> 5] = ss;
        __syncthreads();
        float tot = wsum[0] + wsum[1] + wsum[2] + wsum[3];
        float r = rsqrtf(tot * (1.f / 128.f) + 1e-6f);
        if (seg < 16) g_qn[b][seg][tid]      = v * r * q_gamma[tid];
        else          g_kn[b][seg - 16][tid] = v * r * k_gamma[tid];
    } else {
        g_vn[b][seg - 20][tid] = v;
    }
}

// ---------------- 3) flash-decode: cp.async staged K/V, q in regs ----------
__global__ void __launch_bounds__(128, 6)
attn_k(const float* __restrict__ k_cache, const float* __restrict__ v_cache,
       int split0) {
    const int split = split0 + blockIdx.x;
    const int pair  = blockIdx.y;
    const int b     = pair >> 2;
    const int kv    = pair & 3;
    const int tid   = threadIdx.x;
    const int warp  = tid >> 5;
    const int lane  = tid & 31;

    __shared__ __align__(16) float kst[NSTG][TILE][HD];  // 16 KB
    __shared__ __align__(16) float vst[NSTG][TILE][HD];  // 16 KB
    __shared__ float qs[GROUPS][HD];                     // 2 KB
    __shared__ float s_l[AW][GROUPS];

    // q scaled by scale*log2e, then kept in registers
    for (int i = tid; i < GROUPS * HD; i += 128)
        qs[i >> 7][i & 127] = g_qn[b][kv * GROUPS + (i >> 7)][i & 127] * SCLOG2E;
    __syncthreads();

    float qf[GROUPS][4];
#pragma unroll
    for (int h = 0; h < GROUPS; h++) {
        float4 q4 = *(const float4*)&qs[h][lane * 4];
        qf[h][0] = q4.x; qf[h][1] = q4.y; qf[h][2] = q4.z; qf[h][3] = q4.w;
    }

    float l[GROUPS], acc[GROUPS][4];
#pragma unroll
    for (int h = 0; h < GROUPS; h++) {
        l[h] = 0.f;
        acc[h][0] = acc[h][1] = acc[h][2] = acc[h][3] = 0.f;
    }

    // byte-base pointers; position stride = NKV*HD*4 = 2048 B
    const char* kB = (const char*)k_cache + ((size_t)b * LCACHE * NKV + kv) * HD * 4;
    const char* vB = (const char*)v_cache + ((size_t)b * LCACHE * NKV + kv) * HD * 4;
    const int pt0 = split * SPLIT_LEN;

    // per-thread copy slots: rows {r0, r0+4}, 16B segment seg
    const int r0  = tid >> 5;
    const int seg = tid & 31;

#define ISSUE(t) do {                                                          \
        const int _s = (t) & (NSTG - 1);                                       \
        const size_t _off = (size_t)(pt0 + (t) * TILE) * 2048;                 \
        cp16(&kst[_s][r0][seg * 4],     kB + _off + (size_t)r0 * 2048 + seg * 16);       \
        cp16(&kst[_s][r0 + 4][seg * 4], kB + _off + (size_t)(r0 + 4) * 2048 + seg * 16); \
        cp16(&vst[_s][r0][seg * 4],     vB + _off + (size_t)r0 * 2048 + seg * 16);       \
        cp16(&vst[_s][r0 + 4][seg * 4], vB + _off + (size_t)(r0 + 4) * 2048 + seg * 16); \
    } while (0)

    // prologue: stages 0..NSTG-2
#pragma unroll
    for (int t = 0; t < NSTG - 1; t++) { ISSUE(t); cp_commit(); }

    const bool hi16 = (lane & 16) != 0;
    const bool hi8  = (lane & 8) != 0;
    const bool hi4  = (lane & 4) != 0;

    for (int t = 0; t < NT; t++) {
        if (t + NSTG - 1 < NT) ISSUE(t + NSTG - 1);
        cp_commit();
        cp_wait3();
        __syncthreads();

        const int s = t & (NSTG - 1);
        float4 k0 = ((const float4*)kst[s][2 * warp])[lane];
        float4 k1 = ((const float4*)kst[s][2 * warp + 1])[lane];
        float4 v0 = ((const float4*)vst[s][2 * warp])[lane];
        float4 v1 = ((const float4*)vst[s][2 * warp + 1])[lane];

        // 8 partial dots: value (p0,h) ends at lane 4h, (p1,h) at lane 16+4h
        float a[8];
#pragma unroll
        for (int h = 0; h < GROUPS; h++) {
            a[h]     = qf[h][0] * k0.x + qf[h][1] * k0.y + qf[h][2] * k0.z + qf[h][3] * k0.w;
            a[4 + h] = qf[h][0] * k1.x + qf[h][1] * k1.y + qf[h][2] * k1.z + qf[h][3] * k1.w;
        }

        // pack-exchange reduction: 7 SHFL total
        float b4[4];
#pragma unroll
        for (int u = 0; u < 4; u++) {
            float send = hi16 ? a[u] : a[u + 4];
            float rcv  = __shfl_xor_sync(FULLM, send, 16);
            b4[u] = (hi16 ? a[u + 4] : a[u]) + rcv;
        }
        float c2[2];
#pragma unroll
        for (int u = 0; u < 2; u++) {
            float send = hi8 ? b4[u] : b4[u + 2];
            float rcv  = __shfl_xor_sync(FULLM, send, 8);
            c2[u] = (hi8 ? b4[u + 2] : b4[u]) + rcv;
        }
        {
            float send = hi4 ? c2[0] : c2[1];
            float rcv  = __shfl_xor_sync(FULLM, send, 4);
            c2[0] = (hi4 ? c2[1] : c2[0]) + rcv;
        }
        float d1 = c2[0];
        d1 += __shfl_xor_sync(FULLM, d1, 2);
        d1 += __shfl_xor_sync(FULLM, d1, 1);

        float pw = ex2(d1 - MBIAS);

#pragma unroll
        for (int h = 0; h < GROUPS; h++) {
            float p0w = __shfl_sync(FULLM, pw, 4 * h);
            float p1w = __shfl_sync(FULLM, pw, 16 + 4 * h);
            l[h] += p0w + p1w;
            acc[h][0] = fmaf(p0w, v0.x, fmaf(p1w, v1.x, acc[h][0]));
            acc[h][1] = fmaf(p0w, v0.y, fmaf(p1w, v1.y, acc[h][1]));
            acc[h][2] = fmaf(p0w, v0.z, fmaf(p1w, v1.z, acc[h][2]));
            acc[h][3] = fmaf(p0w, v0.w, fmaf(p1w, v1.w, acc[h][3]));
        }
        __syncthreads();
    }

    // new token (pos LCACHE): warp 3 of the last split, warp-local tail
    if (split == NSPLIT - 1 && warp == AW - 1) {
        float4 k0 = ((const float4*)&g_kn[b][kv][0])[lane];
        float4 v0 = ((const float4*)&g_vn[b][kv][0])[lane];

        float a[8];
#pragma unroll
        for (int h = 0; h < GROUPS; h++) {
            a[h]     = qf[h][0] * k0.x + qf[h][1] * k0.y + qf[h][2] * k0.z + qf[h][3] * k0.w;
            a[4 + h] = a[h];   // dummy p1, weight forced to 0 below
        }
        float b4[4];
#pragma unroll
        for (int u = 0; u < 4; u++) {
            float send = hi16 ? a[u] : a[u + 4];
            float rcv  = __shfl_xor_sync(FULLM, send, 16);
            b4[u] = (hi16 ? a[u + 4] : a[u]) + rcv;
        }
        float c2[2];
#pragma unroll
        for (int u = 0; u < 2; u++) {
            float send = hi8 ? b4[u] : b4[u + 2];
            float rcv  = __shfl_xor_sync(FULLM, send, 8);
            c2[u] = (hi8 ? b4[u + 2] : b4[u]) + rcv;
        }
        {
            float send = hi4 ? c2[0] : c2[1];
            float rcv  = __shfl_xor_sync(FULLM, send, 4);
            c2[0] = (hi4 ? c2[1] : c2[0]) + rcv;
        }
        float d1 = c2[0];
        d1 += __shfl_xor_sync(FULLM, d1, 2);
        d1 += __shfl_xor_sync(FULLM, d1, 1);

        if (hi16) d1 = -CUDART_INF_F;   // p1 invalid -> weight 0
        float pw = ex2(d1 - MBIAS);

#pragma unroll
        for (int h = 0; h < GROUPS; h++) {
            float p0w = __shfl_sync(FULLM, pw, 4 * h);
            l[h] += p0w;
            acc[h][0] = fmaf(p0w, v0.x, acc[h][0]);
            acc[h][1] = fmaf(p0w, v0.y, acc[h][1]);
            acc[h][2] = fmaf(p0w, v0.z, acc[h][2]);
            acc[h][3] = fmaf(p0w, v0.w, acc[h][3]);
        }
    }

    // reduce across warps; reuse kst storage for the per-warp accumulators
    float* sacc = &kst[0][0][0];   // [AW][GROUPS][HD] = 8 KB, fits in kst
#pragma unroll
    for (int h = 0; h < GROUPS; h++) {
        float* dst = sacc + (warp * GROUPS + h) * HD + lane * 4;
        dst[0] = acc[h][0]; dst[1] = acc[h][1]; dst[2] = acc[h][2]; dst[3] = acc[h][3];
        if (lane == 0) s_l[warp][h] = l[h];
    }
    __syncthreads();

    for (int i = tid; i < GROUPS * HD; i += 128) {
        const int h = i >> 7, d = i & 127;
        float num = 0.f;
#pragma unroll
        for (int w = 0; w < AW; w++) num += sacc[(w * GROUPS + h) * HD + d];
        g_pacc[pair][split][h][d] = num;
    }
    if (tid < GROUPS) {
        float tl = 0.f;
#pragma unroll
        for (int w = 0; w < AW; w++) tl += s_l[w][tid];
        g_pl[pair][split][tid] = tl;
    }
}

// ---------------- 4) combine split partials -> attn_out --------------------
__global__ void combine_k() {
    const int idx  = blockIdx.x;
    const int pair = idx >> 2;
    const int g    = idx & 3;
    const int tid  = threadIdx.x;

    __shared__ float s_gl;
    if (tid < 32) {
        float pl = (tid < NSPLIT) ? g_pl[pair][tid][g] : 0.f;
        float gl = pl;
#pragma unroll
        for (int o = 16; o; o >>= 1) gl += __shfl_xor_sync(FULLM, gl, o);
        if (tid == 0) s_gl = gl;
    }
    __syncthreads();

    float num = 0.f;
#pragma unroll
    for (int s = 0; s < NSPLIT; s++) num += g_pacc[pair][s][g][tid];

    const int b = pair >> 2, kv = pair & 3;
    g_attn[b][(kv * GROUPS + g) * HD + tid] = num / s_gl;
}

// ---------------- 5) O projection ------------------------------------------
__global__ void o_gemm_k(const float* __restrict__ w) {
    const int nblk = blockIdx.x;
    const int ks   = blockIdx.y;
    const int tid  = threadIdx.x;

    __shared__ float as_[BATCH][128];
    for (int i = tid; i < BATCH * 128; i += 128) {
        int b = i >> 7, kk = i & 127;
        as_[b][kk] = g_attn[b][ks * 128 + kk];
    }
    __syncthreads();

    const int n = nblk * 128 + tid;
    float acc[BATCH];
#pragma unroll
    for (int b = 0; b < BATCH; b++) acc[b] = 0.f;

    const float* wp = w + (size_t)(ks * 128) * HID + n;
#pragma unroll 2
    for (int kk4 = 0; kk4 < 32; kk4++) {
        float w0 = __ldg(wp + (size_t)(kk4 * 4 + 0) * HID);
        float w1 = __ldg(wp + (size_t)(kk4 * 4 + 1) * HID);
        float w2 = __ldg(wp + (size_t)(kk4 * 4 + 2) * HID);
        float w3 = __ldg(wp + (size_t)(kk4 * 4 + 3) * HID);
#pragma unroll
        for (int b = 0; b < BATCH; b++) {
            float4 h4 = *(const float4*)&as_[b][kk4 * 4];
            acc[b] = fmaf(h4.x, w0, fmaf(h4.y, w1, fmaf(h4.z, w2, fmaf(h4.w, w3, acc[b]))));
        }
    }
#pragma unroll
    for (int b = 0; b < BATCH; b++) g_opart[ks][b][n] = acc[b];
}

// ---------------- 6) sum O partials into d_out -----------------------------
__global__ void ocomb_k(float* __restrict__ out) {
    const int i = blockIdx.x * 256 + threadIdx.x;
    const float* p = &g_opart[0][0][0];
    float v = 0.f;
#pragma unroll
    for (int s = 0; s < KSPLIT; s++) v += p[(size_t)s * BATCH * HID + i];
    out[i] = v;
}

// ---------------- launch ----------------------------------------------------
extern "C" void kernel_launch(void* const* d_in, const int* in_sizes, int n_in,
                              void* d_out, int out_size) {
    const float* hidden  = (const float*)d_in[0];
    const float* k_cache = (const float*)d_in[1];
    const float* v_cache = (const float*)d_in[2];
    const float* w_qkv   = (const float*)d_in[3];
    const float* b_qkv   = (const float*)d_in[4];
    const float* w_o     = (const float*)d_in[5];
    const float* q_gamma = (const float*)d_in[6];
    const float* k_gamma = (const float*)d_in[7];
    float* out = (float*)d_out;

    qkv_gemm_k<<<dim3(QKVW / 128, KSPLIT), 128>>>(hidden, w_qkv);
    rmsnorm_k<<<dim3(QKVW / 128, BATCH), 128>>>(b_qkv, q_gamma, k_gamma);
    // attn split into two launches: keeps attn_k in ncu's captured slot (#4)
    attn_k<<<dim3(NSPLIT / 2, BATCH * NKV), 128>>>(k_cache, v_cache, 0);
    attn_k<<<dim3(NSPLIT / 2, BATCH * NKV), 128>>>(k_cache, v_cache, NSPLIT / 2);
    combine_k<<<BATCH * NKV * GROUPS, 128>>>();
    o_gemm_k<<<dim3(HID / 128, KSPLIT), 128>>>(w_o);
    ocomb_k<<<(BATCH * HID) / 256, 256>>>(out);
}

// round 11
// speedup vs baseline: 1.6767x; 1.0697x over previous
#include <cuda_runtime.h>
#include <math_constants.h>

#define BATCH   32
#define LCACHE  8192
#define NKV     4
#define NH      16
#define HD      128
#define HID     2048
#define QKVW    3072          // 2048 q + 512 k + 512 v
#define GROUPS  4             // NH / NKV
#define NSPLIT  32
#define SPLIT_LEN 256         // LCACHE / NSPLIT
#define KSPLIT  16
#define AW      4             // warps per attn CTA
#define TILE    8             // positions per smem stage (2 per warp)
#define NSTG    4             // cp.async pipeline stages
#define NT      (SPLIT_LEN / TILE)   // 32 tiles per CTA

// scale * log2(e) : (1/sqrt(128)) * 1.4426950408889634
#define SCLOG2E (1.4426950408889634f * 0.08838834764831845f)
// fixed softmax bias in log2 space (validated R5/R7/R10): pw = 2^(s-20)
#define MBIAS   20.0f
#define FULLM   0xffffffffu

__device__ __forceinline__ float ex2(float x) {
    float y; asm("ex2.approx.ftz.f32 %0, %1;" : "=f"(y) : "f"(x)); return y;
}
__device__ __forceinline__ void cp16(void* smem, const void* gmem) {
    unsigned sa = (unsigned)__cvta_generic_to_shared(smem);
    asm volatile("cp.async.cg.shared.global [%0], [%1], 16;" :: "r"(sa), "l"(gmem));
}
__device__ __forceinline__ void cp_commit() {
    asm volatile("cp.async.commit_group;");
}
__device__ __forceinline__ void cp_wait2() {
    asm volatile("cp.async.wait_group 2;");
}

// ---------------- scratch (device globals) ---------------------------------
__device__ float g_qkv_part[KSPLIT][BATCH][QKVW];
__device__ float g_qn[BATCH][NH][HD];
__device__ float g_kn[BATCH][NKV][HD];
__device__ float g_vn[BATCH][NKV][HD];
__device__ float g_pacc[BATCH * NKV][NSPLIT][GROUPS][HD];
__device__ float g_pl[BATCH * NKV][NSPLIT][GROUPS];
__device__ float g_attn[BATCH][HID];
__device__ float g_opart[KSPLIT][BATCH][HID];

// ---------------- 1) QKV GEMM ----------------------------------------------
__global__ void qkv_gemm_k(const float* __restrict__ hidden,
                           const float* __restrict__ w) {
    const int nblk = blockIdx.x;
    const int ks   = blockIdx.y;
    const int tid  = threadIdx.x;

    __shared__ float hs[BATCH][128];
    for (int i = tid; i < BATCH * 128; i += 128) {
        int b = i >> 7, kk = i & 127;
        hs[b][kk] = hidden[b * HID + ks * 128 + kk];
    }
    __syncthreads();

    const int n = nblk * 128 + tid;
    float acc[BATCH];
#pragma unroll
    for (int b = 0; b < BATCH; b++) acc[b] = 0.f;

    const float* wp = w + (size_t)(ks * 128) * QKVW + n;
#pragma unroll 2
    for (int kk4 = 0; kk4 < 32; kk4++) {
        float w0 = __ldg(wp + (size_t)(kk4 * 4 + 0) * QKVW);
        float w1 = __ldg(wp + (size_t)(kk4 * 4 + 1) * QKVW);
        float w2 = __ldg(wp + (size_t)(kk4 * 4 + 2) * QKVW);
        float w3 = __ldg(wp + (size_t)(kk4 * 4 + 3) * QKVW);
#pragma unroll
        for (int b = 0; b < BATCH; b++) {
            float4 h4 = *(const float4*)&hs[b][kk4 * 4];
            acc[b] = fmaf(h4.x, w0, fmaf(h4.y, w1, fmaf(h4.z, w2, fmaf(h4.w, w3, acc[b]))));
        }
    }
#pragma unroll
    for (int b = 0; b < BATCH; b++) g_qkv_part[ks][b][n] = acc[b];
}

// ---------------- 2) sum partials + bias + per-head RMSNorm ----------------
__global__ void rmsnorm_k(const float* __restrict__ b_qkv,
                          const float* __restrict__ q_gamma,
                          const float* __restrict__ k_gamma) {
    const int seg = blockIdx.x;
    const int b   = blockIdx.y;
    const int tid = threadIdx.x;
    const int col = seg * 128 + tid;

    float v = b_qkv[col];
#pragma unroll
    for (int s = 0; s < KSPLIT; s++) v += g_qkv_part[s][b][col];

    if (seg < 20) {
        float ss = v * v;
#pragma unroll
        for (int o = 16; o; o >>= 1) ss += __shfl_xor_sync(FULLM, ss, o);
        __shared__ float wsum[4];
        if ((tid & 31) == 0) wsum[tid >> 5] = ss;
        __syncthreads();
        float tot = wsum[0] + wsum[1] + wsum[2] + wsum[3];
        float r = rsqrtf(tot * (1.f / 128.f) + 1e-6f);
        if (seg < 16) g_qn[b][seg][tid]      = v * r * q_gamma[tid];
        else          g_kn[b][seg - 16][tid] = v * r * k_gamma[tid];
    } else {
        g_vn[b][seg - 20][tid] = v;
    }
}

// ---------------- 3) flash-decode: cp.async staged K/V, 1 barrier/tile -----
__global__ void __launch_bounds__(128, 6)
attn_k(const float* __restrict__ k_cache, const float* __restrict__ v_cache) {
    const int split = blockIdx.x;
    const int pair  = blockIdx.y;
    const int b     = pair >> 2;
    const int kv    = pair & 3;
    const int tid   = threadIdx.x;
    const int warp  = tid >> 5;
    const int lane  = tid & 31;

    __shared__ __align__(16) float kst[NSTG][TILE][HD];  // 16 KB
    __shared__ __align__(16) float vst[NSTG][TILE][HD];  // 16 KB
    __shared__ float qs[GROUPS][HD];                     // 2 KB
    __shared__ float s_l[AW][GROUPS];

    // q scaled by scale*log2e, then kept in registers
    for (int i = tid; i < GROUPS * HD; i += 128)
        qs[i >> 7][i & 127] = g_qn[b][kv * GROUPS + (i >> 7)][i & 127] * SCLOG2E;
    __syncthreads();

    float qf[GROUPS][4];
#pragma unroll
    for (int h = 0; h < GROUPS; h++) {
        float4 q4 = *(const float4*)&qs[h][lane * 4];
        qf[h][0] = q4.x; qf[h][1] = q4.y; qf[h][2] = q4.z; qf[h][3] = q4.w;
    }

    float l[GROUPS], acc[GROUPS][4];
#pragma unroll
    for (int h = 0; h < GROUPS; h++) {
        l[h] = 0.f;
        acc[h][0] = acc[h][1] = acc[h][2] = acc[h][3] = 0.f;
    }

    // byte-base pointers; position stride = NKV*HD*4 = 2048 B
    const char* kB = (const char*)k_cache + ((size_t)b * LCACHE * NKV + kv) * HD * 4;
    const char* vB = (const char*)v_cache + ((size_t)b * LCACHE * NKV + kv) * HD * 4;
    const int pt0 = split * SPLIT_LEN;

    // per-thread copy slots: rows {r0, r0+4}, 16B segment seg
    const int r0  = tid >> 5;
    const int seg = tid & 31;

#define ISSUE(t) do {                                                          \
        const int _s = (t) & (NSTG - 1);                                       \
        const size_t _off = (size_t)(pt0 + (t) * TILE) * 2048;                 \
        cp16(&kst[_s][r0][seg * 4],     kB + _off + (size_t)r0 * 2048 + seg * 16);       \
        cp16(&kst[_s][r0 + 4][seg * 4], kB + _off + (size_t)(r0 + 4) * 2048 + seg * 16); \
        cp16(&vst[_s][r0][seg * 4],     vB + _off + (size_t)r0 * 2048 + seg * 16);       \
        cp16(&vst[_s][r0 + 4][seg * 4], vB + _off + (size_t)(r0 + 4) * 2048 + seg * 16); \
    } while (0)

    // prologue: stages 0..NSTG-2
#pragma unroll
    for (int t = 0; t < NSTG - 1; t++) { ISSUE(t); cp_commit(); }

    const bool hi16 = (lane & 16) != 0;
    const bool hi8  = (lane & 8) != 0;
    const bool hi4  = (lane & 4) != 0;

    for (int t = 0; t < NT; t++) {
        cp_wait2();          // oldest in-flight group (tile t) complete
        __syncthreads();     // visible to all warps; all reads of stage (t-1)%4 done

        if (t + NSTG - 1 < NT) ISSUE(t + NSTG - 1);   // writes stage (t-1)%4
        cp_commit();

        const int s = t & (NSTG - 1);
        float4 k0 = ((const float4*)kst[s][2 * warp])[lane];
        float4 k1 = ((const float4*)kst[s][2 * warp + 1])[lane];
        float4 v0 = ((const float4*)vst[s][2 * warp])[lane];
        float4 v1 = ((const float4*)vst[s][2 * warp + 1])[lane];

        // 8 partial dots: value (p0,h) ends at lane 4h, (p1,h) at lane 16+4h
        float a[8];
#pragma unroll
        for (int h = 0; h < GROUPS; h++) {
            a[h]     = qf[h][0] * k0.x + qf[h][1] * k0.y + qf[h][2] * k0.z + qf[h][3] * k0.w;
            a[4 + h] = qf[h][0] * k1.x + qf[h][1] * k1.y + qf[h][2] * k1.z + qf[h][3] * k1.w;
        }

        // pack-exchange reduction: 7 SHFL total
        float b4[4];
#pragma unroll
        for (int u = 0; u < 4; u++) {
            float send = hi16 ? a[u] : a[u + 4];
            float rcv  = __shfl_xor_sync(FULLM, send, 16);
            b4[u] = (hi16 ? a[u + 4] : a[u]) + rcv;
        }
        float c2[2];
#pragma unroll
        for (int u = 0; u < 2; u++) {
            float send = hi8 ? b4[u] : b4[u + 2];
            float rcv  = __shfl_xor_sync(FULLM, send, 8);
            c2[u] = (hi8 ? b4[u + 2] : b4[u]) + rcv;
        }
        {
            float send = hi4 ? c2[0] : c2[1];
            float rcv  = __shfl_xor_sync(FULLM, send, 4);
            c2[0] = (hi4 ? c2[1] : c2[0]) + rcv;
        }
        float d1 = c2[0];
        d1 += __shfl_xor_sync(FULLM, d1, 2);
        d1 += __shfl_xor_sync(FULLM, d1, 1);

        float pw = ex2(d1 - MBIAS);

#pragma unroll
        for (int h = 0; h < GROUPS; h++) {
            float p0w = __shfl_sync(FULLM, pw, 4 * h);
            float p1w = __shfl_sync(FULLM, pw, 16 + 4 * h);
            l[h] += p0w + p1w;
            acc[h][0] = fmaf(p0w, v0.x, fmaf(p1w, v1.x, acc[h][0]));
            acc[h][1] = fmaf(p0w, v0.y, fmaf(p1w, v1.y, acc[h][1]));
            acc[h][2] = fmaf(p0w, v0.z, fmaf(p1w, v1.z, acc[h][2]));
            acc[h][3] = fmaf(p0w, v0.w, fmaf(p1w, v1.w, acc[h][3]));
        }
    }

    // new token (pos LCACHE): warp 3 of the last split, warp-local tail
    if (split == NSPLIT - 1 && warp == AW - 1) {
        float4 k0 = ((const float4*)&g_kn[b][kv][0])[lane];
        float4 v0 = ((const float4*)&g_vn[b][kv][0])[lane];

        float a[8];
#pragma unroll
        for (int h = 0; h < GROUPS; h++) {
            a[h]     = qf[h][0] * k0.x + qf[h][1] * k0.y + qf[h][2] * k0.z + qf[h][3] * k0.w;
            a[4 + h] = a[h];   // dummy p1, weight forced to 0 below
        }
        float b4[4];
#pragma unroll
        for (int u = 0; u < 4; u++) {
            float send = hi16 ? a[u] : a[u + 4];
            float rcv  = __shfl_xor_sync(FULLM, send, 16);
            b4[u] = (hi16 ? a[u + 4] : a[u]) + rcv;
        }
        float c2[2];
#pragma unroll
        for (int u = 0; u < 2; u++) {
            float send = hi8 ? b4[u] : b4[u + 2];
            float rcv  = __shfl_xor_sync(FULLM, send, 8);
            c2[u] = (hi8 ? b4[u + 2] : b4[u]) + rcv;
        }
        {
            float send = hi4 ? c2[0] : c2[1];
            float rcv  = __shfl_xor_sync(FULLM, send, 4);
            c2[0] = (hi4 ? c2[1] : c2[0]) + rcv;
        }
        float d1 = c2[0];
        d1 += __shfl_xor_sync(FULLM, d1, 2);
        d1 += __shfl_xor_sync(FULLM, d1, 1);

        if (hi16) d1 = -CUDART_INF_F;   // p1 invalid -> weight 0
        float pw = ex2(d1 - MBIAS);

#pragma unroll
        for (int h = 0; h < GROUPS; h++) {
            float p0w = __shfl_sync(FULLM, pw, 4 * h);
            l[h] += p0w;
            acc[h][0] = fmaf(p0w, v0.x, acc[h][0]);
            acc[h][1] = fmaf(p0w, v0.y, acc[h][1]);
            acc[h][2] = fmaf(p0w, v0.z, acc[h][2]);
            acc[h][3] = fmaf(p0w, v0.w, acc[h][3]);
        }
    }

    // reduce across warps; reuse kst stages 0-1 (last tiles read stage 3 only
    // after all warps passed the final barrier; warps are <=1 tile apart and
    // sacc spans stages 0-1 which were last read 2+ tiles before the end)
    float* sacc = &kst[0][0][0];   // [AW][GROUPS][HD] = 8 KB
    __syncthreads();               // all warps done with their mainloop reads
#pragma unroll
    for (int h = 0; h < GROUPS; h++) {
        float* dst = sacc + (warp * GROUPS + h) * HD + lane * 4;
        dst[0] = acc[h][0]; dst[1] = acc[h][1]; dst[2] = acc[h][2]; dst[3] = acc[h][3];
        if (lane == 0) s_l[warp][h] = l[h];
    }
    __syncthreads();

    for (int i = tid; i < GROUPS * HD; i += 128) {
        const int h = i >> 7, d = i & 127;
        float num = 0.f;
#pragma unroll
        for (int w = 0; w < AW; w++) num += sacc[(w * GROUPS + h) * HD + d];
        g_pacc[pair][split][h][d] = num;
    }
    if (tid < GROUPS) {
        float tl = 0.f;
#pragma unroll
        for (int w = 0; w < AW; w++) tl += s_l[w][tid];
        g_pl[pair][split][tid] = tl;
    }
}

// ---------------- 4) combine split partials -> attn_out --------------------
__global__ void combine_k() {
    const int idx  = blockIdx.x;
    const int pair = idx >> 2;
    const int g    = idx & 3;
    const int tid  = threadIdx.x;

    __shared__ float s_gl;
    if (tid < 32) {
        float pl = (tid < NSPLIT) ? g_pl[pair][tid][g] : 0.f;
        float gl = pl;
#pragma unroll
        for (int o = 16; o; o >>= 1) gl += __shfl_xor_sync(FULLM, gl, o);
        if (tid == 0) s_gl = gl;
    }
    __syncthreads();

    float num = 0.f;
#pragma unroll
    for (int s = 0; s < NSPLIT; s++) num += g_pacc[pair][s][g][tid];

    const int b = pair >> 2, kv = pair & 3;
    g_attn[b][(kv * GROUPS + g) * HD + tid] = num / s_gl;
}

// ---------------- 5) O projection ------------------------------------------
__global__ void o_gemm_k(const float* __restrict__ w) {
    const int nblk = blockIdx.x;
    const int ks   = blockIdx.y;
    const int tid  = threadIdx.x;

    __shared__ float as_[BATCH][128];
    for (int i = tid; i < BATCH * 128; i += 128) {
        int b = i >> 7, kk = i & 127;
        as_[b][kk] = g_attn[b][ks * 128 + kk];
    }
    __syncthreads();

    const int n = nblk * 128 + tid;
    float acc[BATCH];
#pragma unroll
    for (int b = 0; b < BATCH; b++) acc[b] = 0.f;

    const float* wp = w + (size_t)(ks * 128) * HID + n;
#pragma unroll 2
    for (int kk4 = 0; kk4 < 32; kk4++) {
        float w0 = __ldg(wp + (size_t)(kk4 * 4 + 0) * HID);
        float w1 = __ldg(wp + (size_t)(kk4 * 4 + 1) * HID);
        float w2 = __ldg(wp + (size_t)(kk4 * 4 + 2) * HID);
        float w3 = __ldg(wp + (size_t)(kk4 * 4 + 3) * HID);
#pragma unroll
        for (int b = 0; b < BATCH; b++) {
            float4 h4 = *(const float4*)&as_[b][kk4 * 4];
            acc[b] = fmaf(h4.x, w0, fmaf(h4.y, w1, fmaf(h4.z, w2, fmaf(h4.w, w3, acc[b]))));
        }
    }
#pragma unroll
    for (int b = 0; b < BATCH; b++) g_opart[ks][b][n] = acc[b];
}

// ---------------- 6) sum O partials into d_out -----------------------------
__global__ void ocomb_k(float* __restrict__ out) {
    const int i = blockIdx.x * 256 + threadIdx.x;
    const float* p = &g_opart[0][0][0];
    float v = 0.f;
#pragma unroll
    for (int s = 0; s < KSPLIT; s++) v += p[(size_t)s * BATCH * HID + i];
    out[i] = v;
}

// ---------------- launch ----------------------------------------------------
extern "C" void kernel_launch(void* const* d_in, const int* in_sizes, int n_in,
                              void* d_out, int out_size) {
    const float* hidden  = (const float*)d_in[0];
    const float* k_cache = (const float*)d_in[1];
    const float* v_cache = (const float*)d_in[2];
    const float* w_qkv   = (const float*)d_in[3];
    const float* b_qkv   = (const float*)d_in[4];
    const float* w_o     = (const float*)d_in[5];
    const float* q_gamma = (const float*)d_in[6];
    const float* k_gamma = (const float*)d_in[7];
    float* out = (float*)d_out;

    qkv_gemm_k<<<dim3(QKVW / 128, KSPLIT), 128>>>(hidden, w_qkv);
    rmsnorm_k<<<dim3(QKVW / 128, BATCH), 128>>>(b_qkv, q_gamma, k_gamma);
    attn_k<<<dim3(NSPLIT, BATCH * NKV), 128>>>(k_cache, v_cache);
    combine_k<<<BATCH * NKV * GROUPS, 128>>>();
    o_gemm_k<<<dim3(HID / 128, KSPLIT), 128>>>(w_o);
    ocomb_k<<<(BATCH * HID) / 256, 256>>>(out);
}

// round 12
// speedup vs baseline: 1.6788x; 1.0013x over previous
#include <cuda_runtime.h>
#include <math_constants.h>

#define BATCH   32
#define LCACHE  8192
#define NKV     4
#define NH      16
#define HD      128
#define HID     2048
#define QKVW    3072          // 2048 q + 512 k + 512 v
#define GROUPS  4             // NH / NKV
#define NSPLIT  32
#define SPLIT_LEN 256         // LCACHE / NSPLIT
#define KSPLIT  16
#define AW      4             // warps per attn CTA
#define TILE    8             // positions per tile (2 per warp)
#define NSTG    4             // per-warp cp.async ring stages
#define NT      (SPLIT_LEN / TILE)   // 32 tiles per CTA

// scale * log2(e) : (1/sqrt(128)) * 1.4426950408889634
#define SCLOG2E (1.4426950408889634f * 0.08838834764831845f)
// fixed softmax bias in log2 space (validated R5/R7/R10/R11): pw = 2^(s-20)
#define MBIAS   20.0f
#define FULLM   0xffffffffu

__device__ __forceinline__ float ex2(float x) {
    float y; asm("ex2.approx.ftz.f32 %0, %1;" : "=f"(y) : "f"(x)); return y;
}
__device__ __forceinline__ void cp16(void* smem, const void* gmem) {
    unsigned sa = (unsigned)__cvta_generic_to_shared(smem);
    asm volatile("cp.async.cg.shared.global [%0], [%1], 16;" :: "r"(sa), "l"(gmem));
}
__device__ __forceinline__ void cp_commit() {
    asm volatile("cp.async.commit_group;");
}
__device__ __forceinline__ void cp_wait2() {
    asm volatile("cp.async.wait_group 2;");
}
__device__ __forceinline__ void cp_wait0() {
    asm volatile("cp.async.wait_group 0;");
}

// ---------------- scratch (device globals) ---------------------------------
__device__ float g_qkv_part[KSPLIT][BATCH][QKVW];
__device__ float g_qn[BATCH][NH][HD];
__device__ float g_kn[BATCH][NKV][HD];
__device__ float g_vn[BATCH][NKV][HD];
__device__ float g_pacc[BATCH * NKV][NSPLIT][GROUPS][HD];
__device__ float g_pl[BATCH * NKV][NSPLIT][GROUPS];
__device__ float g_attn[BATCH][HID];
__device__ float g_opart[KSPLIT][BATCH][HID];

// ---------------- 1) QKV GEMM ----------------------------------------------
__global__ void qkv_gemm_k(const float* __restrict__ hidden,
                           const float* __restrict__ w) {
    const int nblk = blockIdx.x;
    const int ks   = blockIdx.y;
    const int tid  = threadIdx.x;

    __shared__ float hs[BATCH][128];
    for (int i = tid; i < BATCH * 128; i += 128) {
        int b = i >> 7, kk = i & 127;
        hs[b][kk] = hidden[b * HID + ks * 128 + kk];
    }
    __syncthreads();

    const int n = nblk * 128 + tid;
    float acc[BATCH];
#pragma unroll
    for (int b = 0; b < BATCH; b++) acc[b] = 0.f;

    const float* wp = w + (size_t)(ks * 128) * QKVW + n;
#pragma unroll 2
    for (int kk4 = 0; kk4 < 32; kk4++) {
        float w0 = __ldg(wp + (size_t)(kk4 * 4 + 0) * QKVW);
        float w1 = __ldg(wp + (size_t)(kk4 * 4 + 1) * QKVW);
        float w2 = __ldg(wp + (size_t)(kk4 * 4 + 2) * QKVW);
        float w3 = __ldg(wp + (size_t)(kk4 * 4 + 3) * QKVW);
#pragma unroll
        for (int b = 0; b < BATCH; b++) {
            float4 h4 = *(const float4*)&hs[b][kk4 * 4];
            acc[b] = fmaf(h4.x, w0, fmaf(h4.y, w1, fmaf(h4.z, w2, fmaf(h4.w, w3, acc[b]))));
        }
    }
#pragma unroll
    for (int b = 0; b < BATCH; b++) g_qkv_part[ks][b][n] = acc[b];
}

// ---------------- 2) sum partials + bias + per-head RMSNorm ----------------
__global__ void rmsnorm_k(const float* __restrict__ b_qkv,
                          const float* __restrict__ q_gamma,
                          const float* __restrict__ k_gamma) {
    const int seg = blockIdx.x;
    const int b   = blockIdx.y;
    const int tid = threadIdx.x;
    const int col = seg * 128 + tid;

    float v = b_qkv[col];
#pragma unroll
    for (int s = 0; s < KSPLIT; s++) v += g_qkv_part[s][b][col];

    if (seg < 20) {
        float ss = v * v;
#pragma unroll
        for (int o = 16; o; o >>= 1) ss += __shfl_xor_sync(FULLM, ss, o);
        __shared__ float wsum[4];
        if ((tid & 31) == 0) wsum[tid >> 5] = ss;
        __syncthreads();
        float tot = wsum[0] + wsum[1] + wsum[2] + wsum[3];
        float r = rsqrtf(tot * (1.f / 128.f) + 1e-6f);
        if (seg < 16) g_qn[b][seg][tid]      = v * r * q_gamma[tid];
        else          g_kn[b][seg - 16][tid] = v * r * k_gamma[tid];
    } else {
        g_vn[b][seg - 20][tid] = v;
    }
}

// ---------------- 3) flash-decode: warp-private cp.async rings, NO barriers
__global__ void __launch_bounds__(128, 6)
attn_k(const float* __restrict__ k_cache, const float* __restrict__ v_cache) {
    const int split = blockIdx.x;
    const int pair  = blockIdx.y;
    const int b     = pair >> 2;
    const int kv    = pair & 3;
    const int tid   = threadIdx.x;
    const int warp  = tid >> 5;
    const int lane  = tid & 31;

    // per-warp private rings: each warp owns its own stages; each lane reads
    // back exactly the 16B segment it copied -> per-thread cp.async
    // completion (wait_group) is sufficient, no CTA barrier needed.
    __shared__ __align__(16) float kring[AW][NSTG][2][HD];  // 16 KB
    __shared__ __align__(16) float vring[AW][NSTG][2][HD];  // 16 KB
    __shared__ float qs[GROUPS][HD];                        // 2 KB
    __shared__ float s_l[AW][GROUPS];

    // q scaled by scale*log2e, then kept in registers
    for (int i = tid; i < GROUPS * HD; i += 128)
        qs[i >> 7][i & 127] = g_qn[b][kv * GROUPS + (i >> 7)][i & 127] * SCLOG2E;
    __syncthreads();

    float qf[GROUPS][4];
#pragma unroll
    for (int h = 0; h < GROUPS; h++) {
        float4 q4 = *(const float4*)&qs[h][lane * 4];
        qf[h][0] = q4.x; qf[h][1] = q4.y; qf[h][2] = q4.z; qf[h][3] = q4.w;
    }

    float l[GROUPS], acc[GROUPS][4];
#pragma unroll
    for (int h = 0; h < GROUPS; h++) {
        l[h] = 0.f;
        acc[h][0] = acc[h][1] = acc[h][2] = acc[h][3] = 0.f;
    }

    // byte-base pointers; position stride = NKV*HD*4 = 2048 B
    const char* kB = (const char*)k_cache + ((size_t)b * LCACHE * NKV + kv) * HD * 4;
    const char* vB = (const char*)v_cache + ((size_t)b * LCACHE * NKV + kv) * HD * 4;
    const int pt0 = split * SPLIT_LEN;

    // warp w, tile t covers positions pt0 + t*TILE + 2w + {0,1};
    // lane copies its own 16B segment of each row
#define ISSUE(t) do {                                                         \
        const int _s = (t) & (NSTG - 1);                                      \
        const size_t _o = (size_t)(pt0 + (t) * TILE + 2 * warp) * 2048        \
                          + (size_t)lane * 16;                                \
        cp16(&kring[warp][_s][0][lane * 4], kB + _o);                         \
        cp16(&kring[warp][_s][1][lane * 4], kB + _o + 2048);                  \
        cp16(&vring[warp][_s][0][lane * 4], vB + _o);                         \
        cp16(&vring[warp][_s][1][lane * 4], vB + _o + 2048);                  \
    } while (0)

    // prologue: 3 tiles in flight
#pragma unroll
    for (int t = 0; t < NSTG - 1; t++) { ISSUE(t); cp_commit(); }

    const bool hi16 = (lane & 16) != 0;
    const bool hi8  = (lane & 8) != 0;
    const bool hi4  = (lane & 4) != 0;

    for (int t = 0; t < NT; t++) {
        cp_wait2();   // own groups: tile t complete (groups are per-thread)

        const int s = t & (NSTG - 1);
        float4 k0 = ((const float4*)kring[warp][s][0])[lane];
        float4 k1 = ((const float4*)kring[warp][s][1])[lane];
        float4 v0 = ((const float4*)vring[warp][s][0])[lane];
        float4 v1 = ((const float4*)vring[warp][s][1])[lane];

        if (t + NSTG - 1 < NT) ISSUE(t + NSTG - 1);   // stage (t-1)%4: consumed last iter
        cp_commit();                                   // unconditional: keeps group count aligned

        // 8 partial dots: value (p0,h) ends at lane 4h, (p1,h) at lane 16+4h
        float a[8];
#pragma unroll
        for (int h = 0; h < GROUPS; h++) {
            a[h]     = qf[h][0] * k0.x + qf[h][1] * k0.y + qf[h][2] * k0.z + qf[h][3] * k0.w;
            a[4 + h] = qf[h][0] * k1.x + qf[h][1] * k1.y + qf[h][2] * k1.z + qf[h][3] * k1.w;
        }

        // pack-exchange reduction
        float b4[4];
#pragma unroll
        for (int u = 0; u < 4; u++) {
            float send = hi16 ? a[u] : a[u + 4];
            float rcv  = __shfl_xor_sync(FULLM, send, 16);
            b4[u] = (hi16 ? a[u + 4] : a[u]) + rcv;
        }
        float c2[2];
#pragma unroll
        for (int u = 0; u < 2; u++) {
            float send = hi8 ? b4[u] : b4[u + 2];
            float rcv  = __shfl_xor_sync(FULLM, send, 8);
            c2[u] = (hi8 ? b4[u + 2] : b4[u]) + rcv;
        }
        {
            float send = hi4 ? c2[0] : c2[1];
            float rcv  = __shfl_xor_sync(FULLM, send, 4);
            c2[0] = (hi4 ? c2[1] : c2[0]) + rcv;
        }
        float d1 = c2[0];
        d1 += __shfl_xor_sync(FULLM, d1, 2);
        d1 += __shfl_xor_sync(FULLM, d1, 1);

        float pw = ex2(d1 - MBIAS);

#pragma unroll
        for (int h = 0; h < GROUPS; h++) {
            float p0w = __shfl_sync(FULLM, pw, 4 * h);
            float p1w = __shfl_sync(FULLM, pw, 16 + 4 * h);
            l[h] += p0w + p1w;
            acc[h][0] = fmaf(p0w, v0.x, fmaf(p1w, v1.x, acc[h][0]));
            acc[h][1] = fmaf(p0w, v0.y, fmaf(p1w, v1.y, acc[h][1]));
            acc[h][2] = fmaf(p0w, v0.z, fmaf(p1w, v1.z, acc[h][2]));
            acc[h][3] = fmaf(p0w, v0.w, fmaf(p1w, v1.w, acc[h][3]));
        }
    }

    // new token (pos LCACHE): warp 3 of the last split, warp-local tail
    if (split == NSPLIT - 1 && warp == AW - 1) {
        float4 k0 = ((const float4*)&g_kn[b][kv][0])[lane];
        float4 v0 = ((const float4*)&g_vn[b][kv][0])[lane];

        float a[8];
#pragma unroll
        for (int h = 0; h < GROUPS; h++) {
            a[h]     = qf[h][0] * k0.x + qf[h][1] * k0.y + qf[h][2] * k0.z + qf[h][3] * k0.w;
            a[4 + h] = a[h];   // dummy p1, weight forced to 0 below
        }
        float b4[4];
#pragma unroll
        for (int u = 0; u < 4; u++) {
            float send = hi16 ? a[u] : a[u + 4];
            float rcv  = __shfl_xor_sync(FULLM, send, 16);
            b4[u] = (hi16 ? a[u + 4] : a[u]) + rcv;
        }
        float c2[2];
#pragma unroll
        for (int u = 0; u < 2; u++) {
            float send = hi8 ? b4[u] : b4[u + 2];
            float rcv  = __shfl_xor_sync(FULLM, send, 8);
            c2[u] = (hi8 ? b4[u + 2] : b4[u]) + rcv;
        }
        {
            float send = hi4 ? c2[0] : c2[1];
            float rcv  = __shfl_xor_sync(FULLM, send, 4);
            c2[0] = (hi4 ? c2[1] : c2[0]) + rcv;
        }
        float d1 = c2[0];
        d1 += __shfl_xor_sync(FULLM, d1, 2);
        d1 += __shfl_xor_sync(FULLM, d1, 1);

        if (hi16) d1 = -CUDART_INF_F;   // p1 invalid -> weight 0
        float pw = ex2(d1 - MBIAS);

#pragma unroll
        for (int h = 0; h < GROUPS; h++) {
            float p0w = __shfl_sync(FULLM, pw, 4 * h);
            l[h] += p0w;
            acc[h][0] = fmaf(p0w, v0.x, acc[h][0]);
            acc[h][1] = fmaf(p0w, v0.y, acc[h][1]);
            acc[h][2] = fmaf(p0w, v0.z, acc[h][2]);
            acc[h][3] = fmaf(p0w, v0.w, acc[h][3]);
        }
    }

    // drain own in-flight copies before the ring memory is reused as scratch
    cp_wait0();
    __syncthreads();

    // reduce across warps; reuse kring storage for the per-warp accumulators
    float* sacc = &kring[0][0][0][0];   // [AW][GROUPS][HD] = 8 KB
#pragma unroll
    for (int h = 0; h < GROUPS; h++) {
        float* dst = sacc + (warp * GROUPS + h) * HD + lane * 4;
        dst[0] = acc[h][0]; dst[1] = acc[h][1]; dst[2] = acc[h][2]; dst[3] = acc[h][3];
        if (lane == 0) s_l[warp][h] = l[h];
    }
    __syncthreads();

    for (int i = tid; i < GROUPS * HD; i += 128) {
        const int h = i >> 7, d = i & 127;
        float num = 0.f;
#pragma unroll
        for (int w = 0; w < AW; w++) num += sacc[(w * GROUPS + h) * HD + d];
        g_pacc[pair][split][h][d] = num;
    }
    if (tid < GROUPS) {
        float tl = 0.f;
#pragma unroll
        for (int w = 0; w < AW; w++) tl += s_l[w][tid];
        g_pl[pair][split][tid] = tl;
    }
}

// ---------------- 4) combine split partials -> attn_out --------------------
__global__ void combine_k() {
    const int idx  = blockIdx.x;
    const int pair = idx >> 2;
    const int g    = idx & 3;
    const int tid  = threadIdx.x;

    __shared__ float s_gl;
    if (tid < 32) {
        float pl = (tid < NSPLIT) ? g_pl[pair][tid][g] : 0.f;
        float gl = pl;
#pragma unroll
        for (int o = 16; o; o >>= 1) gl += __shfl_xor_sync(FULLM, gl, o);
        if (tid == 0) s_gl = gl;
    }
    __syncthreads();

    float num = 0.f;
#pragma unroll
    for (int s = 0; s < NSPLIT; s++) num += g_pacc[pair][s][g][tid];

    const int b = pair >> 2, kv = pair & 3;
    g_attn[b][(kv * GROUPS + g) * HD + tid] = num / s_gl;
}

// ---------------- 5) O projection ------------------------------------------
__global__ void o_gemm_k(const float* __restrict__ w) {
    const int nblk = blockIdx.x;
    const int ks   = blockIdx.y;
    const int tid  = threadIdx.x;

    __shared__ float as_[BATCH][128];
    for (int i = tid; i < BATCH * 128; i += 128) {
        int b = i >> 7, kk = i & 127;
        as_[b][kk] = g_attn[b][ks * 128 + kk];
    }
    __syncthreads();

    const int n = nblk * 128 + tid;
    float acc[BATCH];
#pragma unroll
    for (int b = 0; b < BATCH; b++) acc[b] = 0.f;

    const float* wp = w + (size_t)(ks * 128) * HID + n;
#pragma unroll 2
    for (int kk4 = 0; kk4 < 32; kk4++) {
        float w0 = __ldg(wp + (size_t)(kk4 * 4 + 0) * HID);
        float w1 = __ldg(wp + (size_t)(kk4 * 4 + 1) * HID);
        float w2 = __ldg(wp + (size_t)(kk4 * 4 + 2) * HID);
        float w3 = __ldg(wp + (size_t)(kk4 * 4 + 3) * HID);
#pragma unroll
        for (int b = 0; b < BATCH; b++) {
            float4 h4 = *(const float4*)&as_[b][kk4 * 4];
            acc[b] = fmaf(h4.x, w0, fmaf(h4.y, w1, fmaf(h4.z, w2, fmaf(h4.w, w3, acc[b]))));
        }
    }
#pragma unroll
    for (int b = 0; b < BATCH; b++) g_opart[ks][b][n] = acc[b];
}

// ---------------- 6) sum O partials into d_out -----------------------------
__global__ void ocomb_k(float* __restrict__ out) {
    const int i = blockIdx.x * 256 + threadIdx.x;
    const float* p = &g_opart[0][0][0];
    float v = 0.f;
#pragma unroll
    for (int s = 0; s < KSPLIT; s++) v += p[(size_t)s * BATCH * HID + i];
    out[i] = v;
}

// ---------------- launch ----------------------------------------------------
extern "C" void kernel_launch(void* const* d_in, const int* in_sizes, int n_in,
                              void* d_out, int out_size) {
    const float* hidden  = (const float*)d_in[0];
    const float* k_cache = (const float*)d_in[1];
    const float* v_cache = (const float*)d_in[2];
    const float* w_qkv   = (const float*)d_in[3];
    const float* b_qkv   = (const float*)d_in[4];
    const float* w_o     = (const float*)d_in[5];
    const float* q_gamma = (const float*)d_in[6];
    const float* k_gamma = (const float*)d_in[7];
    float* out = (float*)d_out;

    qkv_gemm_k<<<dim3(QKVW / 128, KSPLIT), 128>>>(hidden, w_qkv);
    rmsnorm_k<<<dim3(QKVW / 128, BATCH), 128>>>(b_qkv, q_gamma, k_gamma);
    attn_k<<<dim3(NSPLIT, BATCH * NKV), 128>>>(k_cache, v_cache);
    combine_k<<<BATCH * NKV * GROUPS, 128>>>();
    o_gemm_k<<<dim3(HID / 128, KSPLIT), 128>>>(w_o);
    ocomb_k<<<(BATCH * HID) / 256, 256>>>(out);
}